// round 6
// baseline (speedup 1.0000x reference)
#include <cuda_runtime.h>
#include <math.h>

#define BVOL  (128*128*128)
#define VOL   (2*BVOL)          // 4,194,304
#define PLANE (128*128)
#define FVOL  (2*3*BVOL)        // 12,582,912

#define NLCC 400                // 5x5 xy-tiles * 4 z-segs * 2 pairs * 2 batches
#define NREG 294
#define NTV  97
#define NTOT (NLCC + NREG + 2*NTV)   // 888 = 3 full waves at 2 CTAs/SM

__device__ double g_acc[12];    // zero-init; finalizer re-zeros each launch
__device__ unsigned int g_done;
// 0 reg | 1 gg0 2 pp0 3 gp0 | 4 gg1 5 pp1 6 gp1 | 7 tvgp0 8 tvsum0 | 9 tvgp1 10 tvsum1

__device__ __forceinline__ float warpSum(float v) {
#pragma unroll
    for (int o = 16; o; o >>= 1) v += __shfl_down_sync(0xffffffffu, v, o);
    return v;
}

__device__ __forceinline__ double accRead(int i) {
    return atomicAdd(&g_acc[i], 0.0);
}

__global__ void __launch_bounds__(1024, 2)
fused_main(const float* __restrict__ F0,  const float* __restrict__ F0g,
           const float* __restrict__ I0,  const float* __restrict__ I0R,
           const float* __restrict__ I1,  const float* __restrict__ I1R,
           const float* __restrict__ S0,  const float* __restrict__ S0g,
           const float* __restrict__ S1,  const float* __restrict__ S1g,
           float* __restrict__ out) {
    __shared__ float smG[2][32][32];
    __shared__ float smP[2][32][32];
    __shared__ float red[5][32];

    const int tx  = threadIdx.x;          // warp = x-row
    const int ty  = threadIdx.y;
    const int lin = ty * 32 + tx;
    const int lane = lin & 31, wid = lin >> 5;
    const int bid = blockIdx.x;

    if (bid < NLCC) {
        // ---------------- fully fused LCC (pipelined z-loads) ----------------
        int t = bid;
        int pb   = t & 3;  t >>= 2;
        int zseg = t & 3;  t >>= 2;
        int tyid = t % 5;
        int txid = t / 5;
        int pair = pb >> 1, n = pb & 1;
        const float* __restrict__ gt = pair ? I1  : I0;
        const float* __restrict__ pr = pair ? I1R : I0R;
        const int accBase = 1 + 3 * pair;

        const int x0 = txid * 28, y0 = tyid * 28, z0 = zseg * 32;
        const int gx = x0 + tx - 2, gy = y0 + ty - 2;
        const bool colValid = (gx >= 0) && (gx < 128) && (gy >= 0) && (gy < 128);
        const bool inter = (tx >= 2) && (tx < 30) && (ty >= 2) && (ty < 30) &&
                           (gx < 128) && (gy < 128);
        const int cbase = n * BVOL + gy * 128 + gx;    // fits int32

        // z window: g0..g3 = planes z0-2..z0+1, ng = plane z0+2 (prefetched)
        float g0 = 0.f, g1 = 0.f, g2 = 0.f, g3 = 0.f, ng = 0.f;
        float p0 = 0.f, p1 = 0.f, p2 = 0.f, p3 = 0.f, np = 0.f;
        if (colValid) {
            if (z0 >= 2) { g0 = gt[cbase + (z0-2) * PLANE]; p0 = pr[cbase + (z0-2) * PLANE]; }
            if (z0 >= 1) { g1 = gt[cbase + (z0-1) * PLANE]; p1 = pr[cbase + (z0-1) * PLANE]; }
            g2 = gt[cbase + z0 * PLANE];       p2 = pr[cbase + z0 * PLANE];
            g3 = gt[cbase + (z0+1) * PLANE];   p3 = pr[cbase + (z0+1) * PLANE];
            ng = gt[cbase + (z0+2) * PLANE];   np = pr[cbase + (z0+2) * PLANE];
        }

        float agg = 0.f, app = 0.f, agp = 0.f;

#pragma unroll 4
        for (int zi = 0; zi < 32; zi++) {
            const int buf = zi & 1;
            // z-sum with current window (center = g2 = plane z0+zi)
            smG[buf][ty][tx] = ((g0 + g1) + (g2 + g3)) + ng;
            smP[buf][ty][tx] = ((p0 + p1) + (p2 + p3)) + np;

            // prefetch NEXT iteration's leading plane (z0+zi+3) before the bar;
            // consumed one full iteration later -> latency hidden.
            float ng2 = 0.f, np2 = 0.f;
            {
                int zl = z0 + zi + 3;
                if (colValid && zl < 128) {
                    ng2 = gt[cbase + zl * PLANE];
                    np2 = pr[cbase + zl * PLANE];
                }
            }
            __syncthreads();

            float ysG = 0.f, ysP = 0.f;
            if (ty >= 2 && ty < 30) {
                ysG = ((smG[buf][ty-2][tx] + smG[buf][ty-1][tx]) + (smG[buf][ty][tx] + smG[buf][ty+1][tx])) + smG[buf][ty+2][tx];
                ysP = ((smP[buf][ty-2][tx] + smP[buf][ty-1][tx]) + (smP[buf][ty][tx] + smP[buf][ty+1][tx])) + smP[buf][ty+2][tx];
            }
            float gGm2 = __shfl_up_sync(0xffffffffu, ysG, 2);
            float gGm1 = __shfl_up_sync(0xffffffffu, ysG, 1);
            float gGp1 = __shfl_down_sync(0xffffffffu, ysG, 1);
            float gGp2 = __shfl_down_sync(0xffffffffu, ysG, 2);
            float gPm2 = __shfl_up_sync(0xffffffffu, ysP, 2);
            float gPm1 = __shfl_up_sync(0xffffffffu, ysP, 1);
            float gPp1 = __shfl_down_sync(0xffffffffu, ysP, 1);
            float gPp2 = __shfl_down_sync(0xffffffffu, ysP, 2);
            if (inter) {
                float mg = (((gGm2 + gGm1) + (ysG + gGp1)) + gGp2) * 0.008f;  // 1/125
                float mp = (((gPm2 + gPm1) + (ysP + gPp1)) + gPp2) * 0.008f;
                float dg = g2 - mg;
                float dp = p2 - mp;
                agg = fmaf(dg, dg, agg);
                app = fmaf(dp, dp, app);
                agp = fmaf(dg, dp, agp);
            }
            // no trailing sync: next iter uses the other buffer.
            g0 = g1; g1 = g2; g2 = g3; g3 = ng; ng = ng2;
            p0 = p1; p1 = p2; p2 = p3; p3 = np; np = np2;
        }

        agg = warpSum(agg); app = warpSum(app); agp = warpSum(agp);
        if (lane == 0) { red[0][wid] = agg; red[1][wid] = app; red[2][wid] = agp; }
        __syncthreads();
        if (wid == 0) {
            float a = red[0][lane], b = red[1][lane], c = red[2][lane];
            a = warpSum(a); b = warpSum(b); c = warpSum(c);
            if (lane == 0) {
                atomicAdd(&g_acc[accBase + 0], (double)a);
                atomicAdd(&g_acc[accBase + 1], (double)b);
                atomicAdd(&g_acc[accBase + 2], (double)c);
            }
        }
    } else if (bid < NLCC + NREG) {
        // ---------------- reg_field: tight branch-free stream ----------------
        const int R = FVOL / 4;
        const int stride = NREG * 1024;
        float s = 0.f;
        const float4* __restrict__ a4 = (const float4*)F0;
        const float4* __restrict__ b4 = (const float4*)F0g;
#pragma unroll 4
        for (int i = (bid - NLCC) * 1024 + lin; i < R; i += stride) {
            float4 a = a4[i], b = b4[i];
            float d0 = a.x - b.x, d1 = a.y - b.y, d2 = a.z - b.z, d3 = a.w - b.w;
            s += (d0 * d0 + d1 * d1) + (d2 * d2 + d3 * d3);
        }
        s = warpSum(s);
        if (lane == 0) red[0][wid] = s;
        __syncthreads();
        if (wid == 0) {
            float v = warpSum(red[0][lane]);
            if (lane == 0) atomicAdd(&g_acc[0], (double)v);
        }
    } else {
        // ---------------- tversky (one pair per block range) -----------------
        const int which = (bid - NLCC - NREG) / NTV;        // 0 or 1
        const int rb    = (bid - NLCC - NREG) % NTV;
        const float4* __restrict__ g4 = (const float4*)(which ? S1  : S0);
        const float4* __restrict__ p4 = (const float4*)(which ? S1g : S0g);
        const int accBase = 7 + 2 * which;
        const int T = VOL / 4;
        const int stride = NTV * 1024;
        float sgp = 0.f, ssm = 0.f;
#pragma unroll 4
        for (int i = rb * 1024 + lin; i < T; i += stride) {
            float4 a = g4[i], b = p4[i];
            sgp += (a.x * b.x + a.y * b.y) + (a.z * b.z + a.w * b.w);
            ssm += ((a.x + b.x) + (a.y + b.y)) + ((a.z + b.z) + (a.w + b.w));
        }
        sgp = warpSum(sgp); ssm = warpSum(ssm);
        if (lane == 0) { red[0][wid] = sgp; red[1][wid] = ssm; }
        __syncthreads();
        if (wid == 0) {
            float a = warpSum(red[0][lane]);
            float b = warpSum(red[1][lane]);
            if (lane == 0) {
                atomicAdd(&g_acc[accBase + 0], (double)a);
                atomicAdd(&g_acc[accBase + 1], (double)b);
            }
        }
    }

    // -------- last-block finalize ----------------------------------------
    if (lin == 0) {
        __threadfence();
        unsigned int old = atomicAdd(&g_done, 1u);
        if (old == NTOT - 1) {
            double a0 = accRead(0), a1 = accRead(1), a2 = accRead(2), a3 = accRead(3);
            double a4 = accRead(4), a5 = accRead(5), a6 = accRead(6), a7 = accRead(7);
            double a8 = accRead(8), a9 = accRead(9), a10 = accRead(10);

            double reg = sqrt(a0) / (double)FVOL;
            double den0 = a1 * a2; if (den0 < 1e-5) den0 = 1e-5;
            double lcc0 = -((a3 * a3) / den0) / (double)VOL;
            double den1 = a4 * a5; if (den1 < 1e-5) den1 = 1e-5;
            double lcc1 = -((a6 * a6) / den1) / (double)VOL;
            double ds0 = a8;  if (ds0 < 1e-5) ds0 = 1e-5;
            double tv0 = -a7 / ds0;
            double ds1 = a10; if (ds1 < 1e-5) ds1 = 1e-5;
            double tv1 = -a9 / ds1;

            out[0] = (float)(reg + 10.0 * (lcc0 + lcc1) + 10.0 * (tv0 + tv1));

#pragma unroll
            for (int k = 0; k < 12; k++) g_acc[k] = 0.0;
            __threadfence();
            g_done = 0u;
        }
    }
}

extern "C" void kernel_launch(void* const* d_in, const int* in_sizes, int n_in,
                              void* d_out, int out_size) {
    const float* F0  = (const float*)d_in[0];
    const float* F0g = (const float*)d_in[1];
    const float* I0  = (const float*)d_in[2];
    const float* I0R = (const float*)d_in[3];
    const float* I1  = (const float*)d_in[4];
    const float* I1R = (const float*)d_in[5];
    const float* S0  = (const float*)d_in[6];
    const float* S0g = (const float*)d_in[7];
    const float* S1  = (const float*)d_in[8];
    const float* S1g = (const float*)d_in[9];
    float* out = (float*)d_out;

    dim3 blk(32, 32);
    fused_main<<<NTOT, blk>>>(F0, F0g, I0, I0R, I1, I1R, S0, S0g, S1, S1g, out);
}

// round 7
// speedup vs baseline: 1.2652x; 1.2652x over previous
#include <cuda_runtime.h>
#include <math.h>

#define BVOL  (128*128*128)
#define VOL   (2*BVOL)          // 4,194,304
#define PLANE (128*128)
#define FVOL  (2*3*BVOL)        // 12,582,912

#define NLCC 800                // 5x5 xy-tiles * 8 z-segs * 2 pairs * 2 batches
#define NREG 294
#define NTV  97
#define NTOT (NLCC + NREG + 2*NTV)

__device__ double g_acc[12];    // zero-init; finalizer re-zeros each launch
__device__ unsigned int g_done;
// 0 reg | 1 gg0 2 pp0 3 gp0 | 4 gg1 5 pp1 6 gp1 | 7 tvgp0 8 tvsum0 | 9 tvgp1 10 tvsum1

__device__ __forceinline__ float warpSum(float v) {
#pragma unroll
    for (int o = 16; o; o >>= 1) v += __shfl_down_sync(0xffffffffu, v, o);
    return v;
}

__device__ __forceinline__ double accRead(int i) {
    return atomicAdd(&g_acc[i], 0.0);
}

__global__ void __launch_bounds__(1024, 2)
fused_main(const float* __restrict__ F0,  const float* __restrict__ F0g,
           const float* __restrict__ I0,  const float* __restrict__ I0R,
           const float* __restrict__ I1,  const float* __restrict__ I1R,
           const float* __restrict__ S0,  const float* __restrict__ S0g,
           const float* __restrict__ S1,  const float* __restrict__ S1g,
           float* __restrict__ out) {
    __shared__ float2 smZ[2][32][32];   // (G,P) packed
    __shared__ float red[5][32];

    const int tx  = threadIdx.x;          // warp = x-row
    const int ty  = threadIdx.y;
    const int lin = ty * 32 + tx;
    const int lane = lin & 31, wid = lin >> 5;
    const int bid = blockIdx.x;

    if (bid < NLCC) {
        // ---------------- fully fused LCC ----------------
        int t = bid;
        int pb   = t & 3;  t >>= 2;      // pair*2 + batch
        int zseg = t & 7;  t >>= 3;      // 8 z-segments of 16
        int tyid = t % 5;
        int txid = t / 5;
        int pair = pb >> 1, n = pb & 1;
        const float* __restrict__ gt = pair ? I1  : I0;
        const float* __restrict__ pr = pair ? I1R : I0R;
        const int accBase = 1 + 3 * pair;

        const int x0 = txid * 28, y0 = tyid * 28, z0 = zseg * 16;
        const int gx = x0 + tx - 2, gy = y0 + ty - 2;
        const bool colValid = (gx >= 0) && (gx < 128) && (gy >= 0) && (gy < 128);
        const bool inter = (tx >= 2) && (tx < 30) && (ty >= 2) && (ty < 30) &&
                           (gx < 128) && (gy < 128);
        const int cbase = n * BVOL + gy * 128 + gx;

        // 5-plane sliding window: g0..g3 = planes z0-2..z0+1
        float g0 = 0.f, g1 = 0.f, g2 = 0.f, g3 = 0.f;
        float p0 = 0.f, p1 = 0.f, p2 = 0.f, p3 = 0.f;
        if (colValid) {
            if (z0 >= 2) { g0 = gt[cbase + (z0-2) * PLANE]; p0 = pr[cbase + (z0-2) * PLANE]; }
            if (z0 >= 1) { g1 = gt[cbase + (z0-1) * PLANE]; p1 = pr[cbase + (z0-1) * PLANE]; }
            g2 = gt[cbase + z0 * PLANE];       p2 = pr[cbase + z0 * PLANE];
            g3 = gt[cbase + (z0+1) * PLANE];   p3 = pr[cbase + (z0+1) * PLANE];
        }

        float agg = 0.f, app = 0.f, agp = 0.f;

#pragma unroll 4
        for (int zi = 0; zi < 16; zi++) {
            const int buf = zi & 1;
            const int zl  = z0 + zi + 2;
            float ng = 0.f, np = 0.f;
            if (colValid && zl < 128) {
                ng = gt[cbase + zl * PLANE];
                np = pr[cbase + zl * PLANE];
            }
            smZ[buf][ty][tx] = make_float2(((g0 + g1) + (g2 + g3)) + ng,
                                           ((p0 + p1) + (p2 + p3)) + np);
            __syncthreads();

            float ysG = 0.f, ysP = 0.f;
            if (ty >= 2 && ty < 30) {
                float2 a = smZ[buf][ty-2][tx];
                float2 b = smZ[buf][ty-1][tx];
                float2 c = smZ[buf][ty  ][tx];
                float2 d = smZ[buf][ty+1][tx];
                float2 e = smZ[buf][ty+2][tx];
                ysG = ((a.x + b.x) + (c.x + d.x)) + e.x;
                ysP = ((a.y + b.y) + (c.y + d.y)) + e.y;
            }
            float gGm2 = __shfl_up_sync(0xffffffffu, ysG, 2);
            float gGm1 = __shfl_up_sync(0xffffffffu, ysG, 1);
            float gGp1 = __shfl_down_sync(0xffffffffu, ysG, 1);
            float gGp2 = __shfl_down_sync(0xffffffffu, ysG, 2);
            float gPm2 = __shfl_up_sync(0xffffffffu, ysP, 2);
            float gPm1 = __shfl_up_sync(0xffffffffu, ysP, 1);
            float gPp1 = __shfl_down_sync(0xffffffffu, ysP, 1);
            float gPp2 = __shfl_down_sync(0xffffffffu, ysP, 2);
            if (inter) {
                float mg = (((gGm2 + gGm1) + (ysG + gGp1)) + gGp2) * 0.008f;  // 1/125
                float mp = (((gPm2 + gPm1) + (ysP + gPp1)) + gPp2) * 0.008f;
                float dg = g2 - mg;
                float dp = p2 - mp;
                agg = fmaf(dg, dg, agg);
                app = fmaf(dp, dp, app);
                agp = fmaf(dg, dp, agp);
            }
            // no trailing sync: next iter writes the other buffer.
            g0 = g1; g1 = g2; g2 = g3; g3 = ng;
            p0 = p1; p1 = p2; p2 = p3; p3 = np;
        }

        agg = warpSum(agg); app = warpSum(app); agp = warpSum(agp);
        if (lane == 0) { red[0][wid] = agg; red[1][wid] = app; red[2][wid] = agp; }
        __syncthreads();
        if (wid == 0) {
            float a = red[0][lane], b = red[1][lane], c = red[2][lane];
            a = warpSum(a); b = warpSum(b); c = warpSum(c);
            if (lane == 0) {
                atomicAdd(&g_acc[accBase + 0], (double)a);
                atomicAdd(&g_acc[accBase + 1], (double)b);
                atomicAdd(&g_acc[accBase + 2], (double)c);
            }
        }
    } else if (bid < NLCC + NREG) {
        // ---------------- reg_field: branch-free stream ----------------
        const int R = FVOL / 4;
        const int stride = NREG * 1024;
        float s = 0.f;
        const float4* __restrict__ a4 = (const float4*)F0;
        const float4* __restrict__ b4 = (const float4*)F0g;
#pragma unroll 4
        for (int i = (bid - NLCC) * 1024 + lin; i < R; i += stride) {
            float4 a = a4[i], b = b4[i];
            float d0 = a.x - b.x, d1 = a.y - b.y, d2 = a.z - b.z, d3 = a.w - b.w;
            s += (d0 * d0 + d1 * d1) + (d2 * d2 + d3 * d3);
        }
        s = warpSum(s);
        if (lane == 0) red[0][wid] = s;
        __syncthreads();
        if (wid == 0) {
            float v = warpSum(red[0][lane]);
            if (lane == 0) atomicAdd(&g_acc[0], (double)v);
        }
    } else {
        // ---------------- tversky ----------------
        const int which = (bid - NLCC - NREG) / NTV;
        const int rb    = (bid - NLCC - NREG) % NTV;
        const float4* __restrict__ g4 = (const float4*)(which ? S1  : S0);
        const float4* __restrict__ p4 = (const float4*)(which ? S1g : S0g);
        const int accBase = 7 + 2 * which;
        const int T = VOL / 4;
        const int stride = NTV * 1024;
        float sgp = 0.f, ssm = 0.f;
#pragma unroll 4
        for (int i = rb * 1024 + lin; i < T; i += stride) {
            float4 a = g4[i], b = p4[i];
            sgp += (a.x * b.x + a.y * b.y) + (a.z * b.z + a.w * b.w);
            ssm += ((a.x + b.x) + (a.y + b.y)) + ((a.z + b.z) + (a.w + b.w));
        }
        sgp = warpSum(sgp); ssm = warpSum(ssm);
        if (lane == 0) { red[0][wid] = sgp; red[1][wid] = ssm; }
        __syncthreads();
        if (wid == 0) {
            float a = warpSum(red[0][lane]);
            float b = warpSum(red[1][lane]);
            if (lane == 0) {
                atomicAdd(&g_acc[accBase + 0], (double)a);
                atomicAdd(&g_acc[accBase + 1], (double)b);
            }
        }
    }

    // -------- last-block finalize ----------------------------------------
    if (lin == 0) {
        __threadfence();
        unsigned int old = atomicAdd(&g_done, 1u);
        if (old == NTOT - 1) {
            double a0 = accRead(0), a1 = accRead(1), a2 = accRead(2), a3 = accRead(3);
            double a4 = accRead(4), a5 = accRead(5), a6 = accRead(6), a7 = accRead(7);
            double a8 = accRead(8), a9 = accRead(9), a10 = accRead(10);

            double reg = sqrt(a0) / (double)FVOL;
            double den0 = a1 * a2; if (den0 < 1e-5) den0 = 1e-5;
            double lcc0 = -((a3 * a3) / den0) / (double)VOL;
            double den1 = a4 * a5; if (den1 < 1e-5) den1 = 1e-5;
            double lcc1 = -((a6 * a6) / den1) / (double)VOL;
            double ds0 = a8;  if (ds0 < 1e-5) ds0 = 1e-5;
            double tv0 = -a7 / ds0;
            double ds1 = a10; if (ds1 < 1e-5) ds1 = 1e-5;
            double tv1 = -a9 / ds1;

            out[0] = (float)(reg + 10.0 * (lcc0 + lcc1) + 10.0 * (tv0 + tv1));

#pragma unroll
            for (int k = 0; k < 12; k++) g_acc[k] = 0.0;
            __threadfence();
            g_done = 0u;
        }
    }
}

extern "C" void kernel_launch(void* const* d_in, const int* in_sizes, int n_in,
                              void* d_out, int out_size) {
    const float* F0  = (const float*)d_in[0];
    const float* F0g = (const float*)d_in[1];
    const float* I0  = (const float*)d_in[2];
    const float* I0R = (const float*)d_in[3];
    const float* I1  = (const float*)d_in[4];
    const float* I1R = (const float*)d_in[5];
    const float* S0  = (const float*)d_in[6];
    const float* S0g = (const float*)d_in[7];
    const float* S1  = (const float*)d_in[8];
    const float* S1g = (const float*)d_in[9];
    float* out = (float*)d_out;

    dim3 blk(32, 32);
    fused_main<<<NTOT, blk>>>(F0, F0g, I0, I0R, I1, I1R, S0, S0g, S1, S1g, out);
}

// round 8
// speedup vs baseline: 1.3052x; 1.0316x over previous
#include <cuda_runtime.h>
#include <math.h>

#define BVOL  (128*128*128)
#define VOL   (2*BVOL)          // 4,194,304
#define PLANE (128*128)
#define FVOL  (2*3*BVOL)        // 12,582,912

#define NLCC 1760               // 5x11 xy-tiles * 8 z-segs * 2 pairs * 2 batches
#define NREG 364
#define NTV  122
#define NTOT (NLCC + NREG + 2*NTV)   // 2368 = 4 waves at 4 CTAs/SM

__device__ double g_acc[12];    // zero-init; finalizer re-zeros each launch
__device__ unsigned int g_done;
// 0 reg | 1 gg0 2 pp0 3 gp0 | 4 gg1 5 pp1 6 gp1 | 7 tvgp0 8 tvsum0 | 9 tvgp1 10 tvsum1

__device__ __forceinline__ float warpSum(float v) {
#pragma unroll
    for (int o = 16; o; o >>= 1) v += __shfl_down_sync(0xffffffffu, v, o);
    return v;
}

__device__ __forceinline__ double accRead(int i) {
    return atomicAdd(&g_acc[i], 0.0);
}

__global__ void __launch_bounds__(512, 4)
fused_main(const float* __restrict__ F0,  const float* __restrict__ F0g,
           const float* __restrict__ I0,  const float* __restrict__ I0R,
           const float* __restrict__ I1,  const float* __restrict__ I1R,
           const float* __restrict__ S0,  const float* __restrict__ S0g,
           const float* __restrict__ S1,  const float* __restrict__ S1g,
           float* __restrict__ out) {
    __shared__ float2 smZ[2][16][32];   // (G,P) packed
    __shared__ float red[5][16];

    const int tx  = threadIdx.x;          // warp = x-row
    const int ty  = threadIdx.y;          // 0..15
    const int lin = ty * 32 + tx;
    const int lane = lin & 31, wid = lin >> 5;
    const int bid = blockIdx.x;

    if (bid < NLCC) {
        // ---------------- fully fused LCC ----------------
        int t = bid;
        int pb   = t & 3;  t >>= 2;      // pair*2 + batch
        int zseg = t & 7;  t >>= 3;      // 8 z-segments of 16
        int tyid = t % 11;               // 11 y-tiles of 12
        int txid = t / 11;               // 5 x-tiles of 28
        int pair = pb >> 1, n = pb & 1;
        const float* __restrict__ gt = pair ? I1  : I0;
        const float* __restrict__ pr = pair ? I1R : I0R;
        const int accBase = 1 + 3 * pair;

        const int x0 = txid * 28, y0 = tyid * 12, z0 = zseg * 16;
        const int gx = x0 + tx - 2, gy = y0 + ty - 2;
        const bool colValid = (gx >= 0) && (gx < 128) && (gy >= 0) && (gy < 128);
        const bool inter = (tx >= 2) && (tx < 30) && (ty >= 2) && (ty < 14) &&
                           (gx < 128) && (gy < 128);
        const int cbase = n * BVOL + gy * 128 + gx;

        // 5-plane sliding window: g0..g3 = planes z0-2..z0+1
        float g0 = 0.f, g1 = 0.f, g2 = 0.f, g3 = 0.f;
        float p0 = 0.f, p1 = 0.f, p2 = 0.f, p3 = 0.f;
        if (colValid) {
            if (z0 >= 2) { g0 = gt[cbase + (z0-2) * PLANE]; p0 = pr[cbase + (z0-2) * PLANE]; }
            if (z0 >= 1) { g1 = gt[cbase + (z0-1) * PLANE]; p1 = pr[cbase + (z0-1) * PLANE]; }
            g2 = gt[cbase + z0 * PLANE];       p2 = pr[cbase + z0 * PLANE];
            g3 = gt[cbase + (z0+1) * PLANE];   p3 = pr[cbase + (z0+1) * PLANE];
        }

        float agg = 0.f, app = 0.f, agp = 0.f;

#pragma unroll 4
        for (int zi = 0; zi < 16; zi++) {
            const int buf = zi & 1;
            const int zl  = z0 + zi + 2;
            float ng = 0.f, np = 0.f;
            if (colValid && zl < 128) {
                ng = gt[cbase + zl * PLANE];
                np = pr[cbase + zl * PLANE];
            }
            smZ[buf][ty][tx] = make_float2(((g0 + g1) + (g2 + g3)) + ng,
                                           ((p0 + p1) + (p2 + p3)) + np);
            __syncthreads();

            float ysG = 0.f, ysP = 0.f;
            if (ty >= 2 && ty < 14) {
                float2 a = smZ[buf][ty-2][tx];
                float2 b = smZ[buf][ty-1][tx];
                float2 c = smZ[buf][ty  ][tx];
                float2 d = smZ[buf][ty+1][tx];
                float2 e = smZ[buf][ty+2][tx];
                ysG = ((a.x + b.x) + (c.x + d.x)) + e.x;
                ysP = ((a.y + b.y) + (c.y + d.y)) + e.y;
            }
            float gGm2 = __shfl_up_sync(0xffffffffu, ysG, 2);
            float gGm1 = __shfl_up_sync(0xffffffffu, ysG, 1);
            float gGp1 = __shfl_down_sync(0xffffffffu, ysG, 1);
            float gGp2 = __shfl_down_sync(0xffffffffu, ysG, 2);
            float gPm2 = __shfl_up_sync(0xffffffffu, ysP, 2);
            float gPm1 = __shfl_up_sync(0xffffffffu, ysP, 1);
            float gPp1 = __shfl_down_sync(0xffffffffu, ysP, 1);
            float gPp2 = __shfl_down_sync(0xffffffffu, ysP, 2);
            if (inter) {
                float mg = (((gGm2 + gGm1) + (ysG + gGp1)) + gGp2) * 0.008f;  // 1/125
                float mp = (((gPm2 + gPm1) + (ysP + gPp1)) + gPp2) * 0.008f;
                float dg = g2 - mg;
                float dp = p2 - mp;
                agg = fmaf(dg, dg, agg);
                app = fmaf(dp, dp, app);
                agp = fmaf(dg, dp, agp);
            }
            // no trailing sync: next iter writes the other buffer.
            g0 = g1; g1 = g2; g2 = g3; g3 = ng;
            p0 = p1; p1 = p2; p2 = p3; p3 = np;
        }

        agg = warpSum(agg); app = warpSum(app); agp = warpSum(agp);
        if (lane == 0) { red[0][wid] = agg; red[1][wid] = app; red[2][wid] = agp; }
        __syncthreads();
        if (wid == 0) {
            float a = (lane < 16) ? red[0][lane] : 0.f;
            float b = (lane < 16) ? red[1][lane] : 0.f;
            float c = (lane < 16) ? red[2][lane] : 0.f;
            a = warpSum(a); b = warpSum(b); c = warpSum(c);
            if (lane == 0) {
                atomicAdd(&g_acc[accBase + 0], (double)a);
                atomicAdd(&g_acc[accBase + 1], (double)b);
                atomicAdd(&g_acc[accBase + 2], (double)c);
            }
        }
    } else if (bid < NLCC + NREG) {
        // ---------------- reg_field: branch-free stream ----------------
        const int R = FVOL / 4;
        const int stride = NREG * 512;
        float s = 0.f;
        const float4* __restrict__ a4 = (const float4*)F0;
        const float4* __restrict__ b4 = (const float4*)F0g;
#pragma unroll 4
        for (int i = (bid - NLCC) * 512 + lin; i < R; i += stride) {
            float4 a = a4[i], b = b4[i];
            float d0 = a.x - b.x, d1 = a.y - b.y, d2 = a.z - b.z, d3 = a.w - b.w;
            s += (d0 * d0 + d1 * d1) + (d2 * d2 + d3 * d3);
        }
        s = warpSum(s);
        if (lane == 0) red[0][wid] = s;
        __syncthreads();
        if (wid == 0) {
            float v = (lane < 16) ? red[0][lane] : 0.f;
            v = warpSum(v);
            if (lane == 0) atomicAdd(&g_acc[0], (double)v);
        }
    } else {
        // ---------------- tversky ----------------
        const int which = (bid - NLCC - NREG) / NTV;
        const int rb    = (bid - NLCC - NREG) % NTV;
        const float4* __restrict__ g4 = (const float4*)(which ? S1  : S0);
        const float4* __restrict__ p4 = (const float4*)(which ? S1g : S0g);
        const int accBase = 7 + 2 * which;
        const int T = VOL / 4;
        const int stride = NTV * 512;
        float sgp = 0.f, ssm = 0.f;
#pragma unroll 4
        for (int i = rb * 512 + lin; i < T; i += stride) {
            float4 a = g4[i], b = p4[i];
            sgp += (a.x * b.x + a.y * b.y) + (a.z * b.z + a.w * b.w);
            ssm += ((a.x + b.x) + (a.y + b.y)) + ((a.z + b.z) + (a.w + b.w));
        }
        sgp = warpSum(sgp); ssm = warpSum(ssm);
        if (lane == 0) { red[0][wid] = sgp; red[1][wid] = ssm; }
        __syncthreads();
        if (wid == 0) {
            float a = (lane < 16) ? red[0][lane] : 0.f;
            float b = (lane < 16) ? red[1][lane] : 0.f;
            a = warpSum(a); b = warpSum(b);
            if (lane == 0) {
                atomicAdd(&g_acc[accBase + 0], (double)a);
                atomicAdd(&g_acc[accBase + 1], (double)b);
            }
        }
    }

    // -------- last-block finalize ----------------------------------------
    if (lin == 0) {
        __threadfence();
        unsigned int old = atomicAdd(&g_done, 1u);
        if (old == NTOT - 1) {
            double a0 = accRead(0), a1 = accRead(1), a2 = accRead(2), a3 = accRead(3);
            double a4 = accRead(4), a5 = accRead(5), a6 = accRead(6), a7 = accRead(7);
            double a8 = accRead(8), a9 = accRead(9), a10 = accRead(10);

            double reg = sqrt(a0) / (double)FVOL;
            double den0 = a1 * a2; if (den0 < 1e-5) den0 = 1e-5;
            double lcc0 = -((a3 * a3) / den0) / (double)VOL;
            double den1 = a4 * a5; if (den1 < 1e-5) den1 = 1e-5;
            double lcc1 = -((a6 * a6) / den1) / (double)VOL;
            double ds0 = a8;  if (ds0 < 1e-5) ds0 = 1e-5;
            double tv0 = -a7 / ds0;
            double ds1 = a10; if (ds1 < 1e-5) ds1 = 1e-5;
            double tv1 = -a9 / ds1;

            out[0] = (float)(reg + 10.0 * (lcc0 + lcc1) + 10.0 * (tv0 + tv1));

#pragma unroll
            for (int k = 0; k < 12; k++) g_acc[k] = 0.0;
            __threadfence();
            g_done = 0u;
        }
    }
}

extern "C" void kernel_launch(void* const* d_in, const int* in_sizes, int n_in,
                              void* d_out, int out_size) {
    const float* F0  = (const float*)d_in[0];
    const float* F0g = (const float*)d_in[1];
    const float* I0  = (const float*)d_in[2];
    const float* I0R = (const float*)d_in[3];
    const float* I1  = (const float*)d_in[4];
    const float* I1R = (const float*)d_in[5];
    const float* S0  = (const float*)d_in[6];
    const float* S0g = (const float*)d_in[7];
    const float* S1  = (const float*)d_in[8];
    const float* S1g = (const float*)d_in[9];
    float* out = (float*)d_out;

    dim3 blk(32, 16);
    fused_main<<<NTOT, blk>>>(F0, F0g, I0, I0R, I1, I1R, S0, S0g, S1, S1g, out);
}